// round 4
// baseline (speedup 1.0000x reference)
#include <cuda_runtime.h>
#include <stdint.h>

#define BB 16
#define AA 12
#define HH 64
#define WW 64
#define GG 64
#define NN (AA*HH*WW)        /* 49152 anchors per batch */
#define TOT (BB*NN)          /* 786432 */
#define NBUCK 8192
#define SENT 0xFFFFFFFFu
#define CAP  4096            /* boundary-bucket candidate capacity per row */

// ---------------- scratch (static __device__, no allocation) ----------------
__device__ unsigned g_ubuf[TOT];        // 23-bit mantissa of r for label-0 elems, else SENT
__device__ unsigned g_hist[BB*NBUCK];   // per-row histogram over u>>10
__device__ unsigned g_pos, g_neg;       // global pos/neg counts
__device__ int      g_T[BB];            // per-row boundary bucket (-1 = none)
__device__ unsigned g_S[BB];            // count strictly above boundary bucket
__device__ unsigned g_cutoff;
__device__ int      g_flag;             // neg_cnt > cutoff
__device__ unsigned g_bcnt[BB];         // boundary candidates per row
__device__ unsigned g_bu [BB*CAP];      // boundary candidate u values
__device__ int      g_bidx[BB*CAP];     // boundary candidate indices

// ------- Threefry-2x32-20, key=(0,42), PARTITIONABLE layout -----------------
__device__ __forceinline__ unsigned threefry_bits(unsigned i) {
    unsigned x0 = 0u, x1 = i;
    const unsigned k0 = 0u, k1 = 42u, k2 = 0x1BD11BDAu ^ 0u ^ 42u;
    x0 += k0; x1 += k1;
#define TFR(r) { x0 += x1; x1 = __funnelshift_l(x1, x1, (r)); x1 ^= x0; }
    TFR(13) TFR(15) TFR(26) TFR(6)   x0 += k1; x1 += k2 + 1u;
    TFR(17) TFR(29) TFR(16) TFR(24)  x0 += k2; x1 += k0 + 2u;
    TFR(13) TFR(15) TFR(26) TFR(6)   x0 += k0; x1 += k1 + 3u;
    TFR(17) TFR(29) TFR(16) TFR(24)  x0 += k1; x1 += k2 + 4u;
    TFR(13) TFR(15) TFR(26) TFR(6)   x0 += k2; x1 += k0 + 5u;
#undef TFR
    return x0 ^ x1;
}

// ---------------- kernel 0: zero scratch (vectorized) -----------------------
__global__ void zero_kernel() {
    int i = blockIdx.x * blockDim.x + threadIdx.x;   // 128*256 = 32768 threads
    ((uint4*)g_hist)[i] = make_uint4(0u,0u,0u,0u);   // 32768 uint4 = 131072 words
    if (i < BB) g_bcnt[i] = 0u;
    if (i == 0) { g_pos = 0u; g_neg = 0u; }
}

// ---------------- kernel 1: IoU / labels / targets / PRNG / hist -----------
// 4 anchors per thread. Division-free inner loop with conservative FMA guard;
// exact __fdiv_rn on guard hit keeps results bit-identical to reference.
__global__ void __launch_bounds__(256) main_kernel(
        const float* __restrict__ gt,       // (B,G,4)
        const float* __restrict__ anchors,  // (N,4)
        float* __restrict__ out)            // (B,N,5)
{
    __shared__ float4 s_gb[GG];    // (gx0, gy0, gx1, gy1)
    __shared__ float  s_ga[GG];    // gt area
    __shared__ float4 s_g0[GG];    // raw batch-0 gt boxes (targets use these!)

    const int b = blockIdx.y;
    const int t = threadIdx.x;

    if (t < GG) {
        const float4 gp = *(const float4*)(gt + ((size_t)b*GG + t)*4);
        s_gb[t] = make_float4(gp.x, gp.y,
                              __fadd_rn(gp.x, gp.z), __fadd_rn(gp.y, gp.w));
        s_ga[t] = __fmul_rn(gp.z, gp.w);
    } else if (t < 2*GG) {
        int g = t - GG;
        s_g0[g] = *(const float4*)(gt + (size_t)g*4);   // batch 0 quirk
    }
    __syncthreads();

    const int n0 = (blockIdx.x * 256 + t) * 4;   // four consecutive anchors

    float4 a[4];
    float ax1[4], ay1[4], aarea[4], best[4], bsl[4];
    int bg[4];
#pragma unroll
    for (int k = 0; k < 4; ++k) {
        a[k] = *(const float4*)(anchors + (size_t)(n0 + k)*4);
        ax1[k]   = __fadd_rn(a[k].x, a[k].z);
        ay1[k]   = __fadd_rn(a[k].y, a[k].w);
        aarea[k] = __fmul_rn(a[k].z, a[k].w);
        best[k]  = -1.0f;
        bsl[k]   = -1.0f;
        bg[k]    = 0;
    }

#pragma unroll 2
    for (int g = 0; g < GG; ++g) {
        const float4 gb = s_gb[g];
        const float  ga = s_ga[g];
#pragma unroll
        for (int k = 0; k < 4; ++k) {
            float iw = fmaxf(0.f, __fsub_rn(fminf(ax1[k], gb.z), fmaxf(a[k].x, gb.x)));
            float ih = fmaxf(0.f, __fsub_rn(fminf(ay1[k], gb.w), fmaxf(a[k].y, gb.y)));
            float inter = __fmul_rn(iw, ih);
            float uni   = __fsub_rn(__fadd_rn(aarea[k], ga), inter);
            if (__fmaf_rn(-bsl[k], uni, inter) >= 0.f) {   // conservative, rare
                float ov = __fdiv_rn(inter, uni);
                if (ov == 0.f) ov = 1e-10f;
                if (ov > best[k]) {
                    best[k] = ov; bg[k] = g;
                    bsl[k] = __fmul_rn(best[k], 0.99999952f);  // 1 - 2^-21
                }
            }
        }
    }

    const float L = 63.0f;
    int myp = 0, myn = 0;

#pragma unroll
    for (int k = 0; k < 4; ++k) {
        const bool keep =
            (a[k].x >= 0.f) && (a[k].y >= 0.f) && (a[k].z >= 0.f) && (a[k].w >= 0.f) &&
            (a[k].x <= L) && (a[k].y <= L) &&
            (__fsub_rn(ax1[k], 1.0f) <= L) &&
            (__fsub_rn(ay1[k], 1.0f) <= L);

        float label = -1.0f;
        bool lab0 = false;
        if (keep) {
            if (best[k] >= 0.7f)       label = 1.0f;
            else if (best[k] <= 0.3f) { label = 0.0f; lab0 = true; }
            myp += (best[k] > 0.7f);
            myn += (best[k] < 0.3f);
        }

        const size_t i = (size_t)b*NN + (n0 + k);
        float* op = out + i*5;
        op[0] = label;
        if (keep) {
            const float4 g0 = s_g0[bg[k]];
            op[1] = __fsub_rn(a[k].x, __fmul_rn(g0.x, 0.0625f));
            op[2] = __fsub_rn(a[k].y, __fmul_rn(g0.y, 0.0625f));
            op[3] = __fsub_rn(a[k].z, __fmul_rn(g0.z, 0.0625f));
            op[4] = __fsub_rn(a[k].w, __fmul_rn(g0.w, 0.0625f));
        } else {
            op[1] = 0.f; op[2] = 0.f; op[3] = 0.f; op[4] = 0.f;
        }

        unsigned u = SENT;
        if (lab0) {
            unsigned bits = threefry_bits((unsigned)i);
            u = bits >> 9;
            atomicAdd(&g_hist[b*NBUCK + (u >> 10)], 1u);
        }
        g_ubuf[i] = u;
    }

    for (int o = 16; o > 0; o >>= 1) {
        myp += __shfl_down_sync(0xFFFFFFFFu, myp, o);
        myn += __shfl_down_sync(0xFFFFFFFFu, myn, o);
    }
    if ((t & 31) == 0) {
        if (myp) atomicAdd(&g_pos, (unsigned)myp);
        if (myn) atomicAdd(&g_neg, (unsigned)myn);
    }
}

// ---------------- kernel 2: parallel boundary-bucket search -----------------
// 16 blocks (one per row), 256 threads: each thread sums 32 descending buckets,
// block-scan over chunk sums, unique boundary thread refines its chunk.
__global__ void __launch_bounds__(256) scan_kernel() {
    const int b = blockIdx.x;
    const int t = threadIdx.x;

    const unsigned pos = g_pos, negc = g_neg;
    const unsigned cutoff = (unsigned)max(1, 3 * (int)pos);
    if (b == 0 && t == 0) {
        g_cutoff = cutoff;
        g_flag   = (negc > cutoff) ? 1 : 0;
    }
    if (negc <= cutoff) { if (t == 0) g_T[b] = -1; return; }

    const unsigned* hrow = g_hist + b*NBUCK;
    const int hi = (NBUCK - 1) - t*32;   // descending chunk: buckets [hi-31 .. hi]
    unsigned s = 0;
#pragma unroll
    for (int k = 0; k < 32; ++k) s += hrow[hi - k];

    __shared__ unsigned sh[256];
    sh[t] = s;
    __syncthreads();
    // inclusive scan over chunks (descending-bucket order)
    for (int o = 1; o < 256; o <<= 1) {
        unsigned add = (t >= o) ? sh[t - o] : 0u;
        __syncthreads();
        sh[t] += add;
        __syncthreads();
    }
    const unsigned incl = sh[t];
    const unsigned excl = incl - s;

    if (excl < cutoff && incl >= cutoff) {   // unique thread
        unsigned acc = excl;
        int T = hi; unsigned S = excl;
        for (int k = 0; k < 32; ++k) {
            unsigned v = hrow[hi - k];
            if (acc + v >= cutoff) { T = hi - k; S = acc; break; }
            acc += v;
        }
        g_T[b] = T; g_S[b] = S;
    }
}

// ---------------- kernel 3a: bulk disable + boundary collect ---------------
__global__ void __launch_bounds__(256) bulk_kernel(float* __restrict__ out) {
    if (!g_flag) return;
    const int b = blockIdx.y;
    const int T = g_T[b];

    const unsigned* row = g_ubuf + (size_t)b*NN;
    const int j0 = (blockIdx.x * 256 + threadIdx.x) * 4;
    const uint4 u4 = *(const uint4*)(row + j0);

    const unsigned uv[4] = {u4.x, u4.y, u4.z, u4.w};
#pragma unroll
    for (int k = 0; k < 4; ++k) {
        unsigned u = uv[k];
        if (u == SENT) continue;
        int bucket = (int)(u >> 10);
        if (bucket < T) {
            out[((size_t)b*NN + (j0 + k))*5] = -1.0f;
        } else if (bucket == T) {
            unsigned p = atomicAdd(&g_bcnt[b], 1u);
            if (p < CAP) { g_bu[b*CAP + p] = u; g_bidx[b*CAP + p] = j0 + k; }
        }
    }
}

// ---------------- kernel 3b: boundary fine-rank -----------------------------
__global__ void __launch_bounds__(256) fine_kernel(float* __restrict__ out) {
    if (!g_flag) return;
    const int b = blockIdx.x;
    if (g_T[b] < 0) return;

    __shared__ unsigned s_u[2048];
    __shared__ int      s_idx[2048];

    const unsigned mraw = g_bcnt[b];
    const unsigned S = g_S[b];
    const unsigned cutoff = g_cutoff;

    if (mraw <= 2048) {
        const int m = (int)mraw;
        for (int a = threadIdx.x; a < m; a += 256) {
            s_u[a] = g_bu[b*CAP + a];
            s_idx[a] = g_bidx[b*CAP + a];
        }
        __syncthreads();
        for (int a = threadIdx.x; a < m; a += 256) {
            unsigned ua = s_u[a]; int ia = s_idx[a];
            unsigned cnt = S;
            for (int k = 0; k < m; ++k) {
                unsigned ub = s_u[k];
                if (ub > ua || (ub == ua && s_idx[k] < ia)) cnt++;
            }
            if (cnt >= cutoff) out[((size_t)b*NN + ia)*5] = -1.0f;
        }
    } else {
        // Degenerate fallback: per-element row scan on the boundary bucket.
        const int T = g_T[b];
        const unsigned* row = g_ubuf + (size_t)b*NN;
        for (int a = threadIdx.x; a < NN; a += 256) {
            unsigned ua = row[a];
            if (ua == SENT || (int)(ua >> 10) != T) continue;
            unsigned cnt = S;
            for (int j = 0; j < NN; ++j) {
                unsigned uj = row[j];
                if (uj != SENT && (int)(uj >> 10) == T &&
                    (uj > ua || (uj == ua && j < a))) cnt++;
            }
            if (cnt >= cutoff) out[((size_t)b*NN + a)*5] = -1.0f;
        }
    }
}

// ---------------- launch ----------------------------------------------------
extern "C" void kernel_launch(void* const* d_in, const int* in_sizes, int n_in,
                              void* d_out, int out_size) {
    const float* gt      = (const float*)d_in[1];
    const float* anchors = (const float*)d_in[2];
    for (int k = 0; k < n_in; ++k) {
        if (in_sizes[k] == BB*GG*4) gt      = (const float*)d_in[k];
        if (in_sizes[k] == NN*4)    anchors = (const float*)d_in[k];
    }
    float* out = (float*)d_out;

    zero_kernel<<<128, 256>>>();
    dim3 mgrid(NN/1024, BB);               // 4 anchors per thread
    main_kernel<<<mgrid, 256>>>(gt, anchors, out);
    scan_kernel<<<BB, 256>>>();
    dim3 bgrid(NN/1024, BB);               // 4 words per thread, uint4
    bulk_kernel<<<bgrid, 256>>>(out);
    fine_kernel<<<BB, 256>>>(out);
}

// round 5
// speedup vs baseline: 1.3345x; 1.3345x over previous
#include <cuda_runtime.h>
#include <stdint.h>

#define BB 16
#define AA 12
#define HH 64
#define WW 64
#define GG 64
#define NN (AA*HH*WW)        /* 49152 anchors per batch */
#define TOT (BB*NN)          /* 786432 */
#define NBUCK 8192
#define SENT 0xFFFFFFFFu
#define CAP  4096

// ---------------- scratch (static __device__, no allocation) ----------------
__device__ unsigned g_ubuf[TOT];
__device__ unsigned g_hist[BB*NBUCK];
__device__ unsigned g_pos, g_neg;
__device__ int      g_T[BB];
__device__ unsigned g_S[BB];
__device__ unsigned g_cutoff;
__device__ int      g_flag;
__device__ unsigned g_bcnt[BB];
__device__ unsigned g_bu [BB*CAP];
__device__ int      g_bidx[BB*CAP];

// ------- Threefry-2x32-20, key=(0,42), PARTITIONABLE layout -----------------
__device__ __forceinline__ unsigned threefry_bits(unsigned i) {
    unsigned x0 = 0u, x1 = i;
    const unsigned k0 = 0u, k1 = 42u, k2 = 0x1BD11BDAu ^ 0u ^ 42u;
    x0 += k0; x1 += k1;
#define TFR(r) { x0 += x1; x1 = __funnelshift_l(x1, x1, (r)); x1 ^= x0; }
    TFR(13) TFR(15) TFR(26) TFR(6)   x0 += k1; x1 += k2 + 1u;
    TFR(17) TFR(29) TFR(16) TFR(24)  x0 += k2; x1 += k0 + 2u;
    TFR(13) TFR(15) TFR(26) TFR(6)   x0 += k0; x1 += k1 + 3u;
    TFR(17) TFR(29) TFR(16) TFR(24)  x0 += k1; x1 += k2 + 4u;
    TFR(13) TFR(15) TFR(26) TFR(6)   x0 += k2; x1 += k0 + 5u;
#undef TFR
    return x0 ^ x1;
}

// ---------------- kernel 0: zero scratch ------------------------------------
__global__ void zero_kernel() {
    int i = blockIdx.x * blockDim.x + threadIdx.x;
    ((uint4*)g_hist)[i] = make_uint4(0u,0u,0u,0u);
    if (i < BB) g_bcnt[i] = 0u;
    if (i == 0) { g_pos = 0u; g_neg = 0u; }
}

// ---------------- kernel 1: IoU / labels / targets / PRNG / hist ------------
// Block = 256 threads <-> (i_loc 0..3, j 0..63); fixed a (blockIdx.y), b (z),
// i0 = blockIdx.x*4. Separable IoU: iw depends on (j,g) only, ih on (i,g) only
// (anchor meshgrid structure; values taken from the real anchors tensor, so
// every arithmetic op is bit-identical to the reference). Division-free inner
// loop with conservative FMA guard; exact __fdiv_rn on guard hit.
// Output staged in shared, written as coalesced float4s.
__global__ void __launch_bounds__(256) main_kernel(
        const float* __restrict__ gt,       // (B,G,4)
        const float* __restrict__ anchors,  // (N,4)
        float* __restrict__ out)            // (B,N,5)
{
    __shared__ float4 s_gb[GG];        // (gx0, gy0, gx1, gy1)
    __shared__ float  s_ga[GG];        // gt area
    __shared__ float4 s_g0[GG];        // raw batch-0 gt boxes (targets quirk)
    __shared__ float  s_ax0[WW], s_ax1[WW];
    __shared__ float  s_ay0[4],  s_ay1[4];
    __shared__ float  s_iw[GG*WW];     // [g][j], 16KB
    __shared__ float  s_ih[GG*4];      // [g][i_loc]
    __shared__ float  s_out[256*5];    // staged output

    const int b  = blockIdx.z;
    const int a  = blockIdx.y;
    const int i0 = blockIdx.x * 4;
    const int t  = threadIdx.x;
    const int j     = t & 63;
    const int i_loc = t >> 6;

    const float4* anc4 = (const float4*)anchors;

    // ---- phase 1: stage gt + anchor row/col data ----
    if (t < GG) {
        const float4 gp = *(const float4*)(gt + ((size_t)b*GG + t)*4);
        s_gb[t] = make_float4(gp.x, gp.y,
                              __fadd_rn(gp.x, gp.z), __fadd_rn(gp.y, gp.w));
        s_ga[t] = __fmul_rn(gp.z, gp.w);
    } else if (t < 2*GG) {
        s_g0[t - GG] = *(const float4*)(gt + (size_t)(t - GG)*4);  // batch 0
    } else if (t < 192) {
        int jj = t - 128;
        float4 v = anc4[(a*HH + i0)*WW + jj];       // x0(j), w: i-invariant
        s_ax0[jj] = v.x;
        s_ax1[jj] = __fadd_rn(v.x, v.z);
    } else if (t < 196) {
        int k = t - 192;
        float4 v = anc4[(a*HH + i0 + k)*WW];        // y0(i), h: j-invariant
        s_ay0[k] = v.y;
        s_ay1[k] = __fadd_rn(v.y, v.w);
    }
    __syncthreads();

    // ---- phase 2: precompute separable iw / ih ----
    {
        int g = t >> 2, k = t & 3;
        s_ih[t] = fmaxf(0.f, __fsub_rn(fminf(s_ay1[k], s_gb[g].w),
                                       fmaxf(s_ay0[k], s_gb[g].y)));
    }
    {
        const float ax0 = s_ax0[j], ax1 = s_ax1[j];
#pragma unroll
        for (int r = 0; r < 16; ++r) {
            int g = r*4 + i_loc;
            const float4 gb = s_gb[g];
            s_iw[g*64 + j] = fmaxf(0.f, __fsub_rn(fminf(ax1, gb.z),
                                                  fmaxf(ax0, gb.x)));
        }
    }
    __syncthreads();

    // ---- own anchor ----
    const int n = (a*HH + (i0 + i_loc))*WW + j;     // index within batch
    const float4 A = anc4[n];
    const float aarea = __fmul_rn(A.z, A.w);

    float best = -1.0f, bsl = -1.0f;
    int   bg = 0;

#pragma unroll 4
    for (int g = 0; g < GG; ++g) {
        float inter = __fmul_rn(s_iw[g*64 + j], s_ih[g*4 + i_loc]);
        float uni   = __fsub_rn(__fadd_rn(aarea, s_ga[g]), inter);
        if (__fmaf_rn(-bsl, uni, inter) >= 0.f) {   // conservative, rare
            float ov = __fdiv_rn(inter, uni);
            if (ov == 0.f) ov = 1e-10f;
            if (ov > best) {
                best = ov; bg = g;
                bsl = __fmul_rn(best, 0.99999952f); // 1 - 2^-21
            }
        }
    }

    // ---- epilogue ----
    const float L = 63.0f;
    const float ax1v = __fadd_rn(A.x, A.z);
    const float ay1v = __fadd_rn(A.y, A.w);
    const bool keep =
        (A.x >= 0.f) && (A.y >= 0.f) && (A.z >= 0.f) && (A.w >= 0.f) &&
        (A.x <= L) && (A.y <= L) &&
        (__fsub_rn(ax1v, 1.0f) <= L) && (__fsub_rn(ay1v, 1.0f) <= L);

    float label = -1.0f;
    bool pos = false, neg = false, lab0 = false;
    if (keep) {
        if (best >= 0.7f)       label = 1.0f;
        else if (best <= 0.3f) { label = 0.0f; lab0 = true; }
        pos = (best > 0.7f);
        neg = (best < 0.3f);
    }

    float* so = s_out + t*5;
    so[0] = label;
    if (keep) {
        const float4 g0 = s_g0[bg];
        so[1] = __fsub_rn(A.x, __fmul_rn(g0.x, 0.0625f));
        so[2] = __fsub_rn(A.y, __fmul_rn(g0.y, 0.0625f));
        so[3] = __fsub_rn(A.z, __fmul_rn(g0.z, 0.0625f));
        so[4] = __fsub_rn(A.w, __fmul_rn(g0.w, 0.0625f));
    } else {
        so[1] = 0.f; so[2] = 0.f; so[3] = 0.f; so[4] = 0.f;
    }

    const size_t i_glob = (size_t)b*NN + n;
    unsigned u = SENT;
    if (lab0) {
        u = threefry_bits((unsigned)i_glob) >> 9;
        atomicAdd(&g_hist[b*NBUCK + (u >> 10)], 1u);
    }
    g_ubuf[i_glob] = u;          // coalesced (consecutive t -> consecutive n)

    unsigned bp = __ballot_sync(0xFFFFFFFFu, pos);
    unsigned bn = __ballot_sync(0xFFFFFFFFu, neg);
    if ((t & 31) == 0) {
        if (bp) atomicAdd(&g_pos, (unsigned)__popc(bp));
        if (bn) atomicAdd(&g_neg, (unsigned)__popc(bn));
    }

    __syncthreads();
    // coalesced write: block's 256 anchors are contiguous -> 1280 floats
    const float4* so4 = (const float4*)s_out;
    float4* o4 = (float4*)(out + (size_t)(((b*AA + a)*HH + i0)*WW)*5);
    o4[t] = so4[t];
    if (t < 64) o4[256 + t] = so4[256 + t];
}

// ---------------- kernel 2: parallel boundary-bucket search -----------------
__global__ void __launch_bounds__(256) scan_kernel() {
    const int b = blockIdx.x;
    const int t = threadIdx.x;

    const unsigned pos = g_pos, negc = g_neg;
    const unsigned cutoff = (unsigned)max(1, 3 * (int)pos);
    if (b == 0 && t == 0) {
        g_cutoff = cutoff;
        g_flag   = (negc > cutoff) ? 1 : 0;
    }
    if (negc <= cutoff) { if (t == 0) g_T[b] = -1; return; }

    const unsigned* hrow = g_hist + b*NBUCK;
    const int hi = (NBUCK - 1) - t*32;
    unsigned s = 0;
#pragma unroll
    for (int k = 0; k < 32; ++k) s += hrow[hi - k];

    __shared__ unsigned sh[256];
    sh[t] = s;
    __syncthreads();
    for (int o = 1; o < 256; o <<= 1) {
        unsigned add = (t >= o) ? sh[t - o] : 0u;
        __syncthreads();
        sh[t] += add;
        __syncthreads();
    }
    const unsigned incl = sh[t];
    const unsigned excl = incl - s;

    if (excl < cutoff && incl >= cutoff) {
        unsigned acc = excl;
        int T = hi; unsigned S = excl;
        for (int k = 0; k < 32; ++k) {
            unsigned v = hrow[hi - k];
            if (acc + v >= cutoff) { T = hi - k; S = acc; break; }
            acc += v;
        }
        g_T[b] = T; g_S[b] = S;
    }
}

// ---------------- kernel 3a: bulk disable + boundary collect ----------------
__global__ void __launch_bounds__(256) bulk_kernel(float* __restrict__ out) {
    if (!g_flag) return;
    const int b = blockIdx.y;
    const int T = g_T[b];

    const unsigned* row = g_ubuf + (size_t)b*NN;
    const int j0 = (blockIdx.x * 256 + threadIdx.x) * 4;
    const uint4 u4 = *(const uint4*)(row + j0);

    const unsigned uv[4] = {u4.x, u4.y, u4.z, u4.w};
#pragma unroll
    for (int k = 0; k < 4; ++k) {
        unsigned u = uv[k];
        if (u == SENT) continue;
        int bucket = (int)(u >> 10);
        if (bucket < T) {
            out[((size_t)b*NN + (j0 + k))*5] = -1.0f;
        } else if (bucket == T) {
            unsigned p = atomicAdd(&g_bcnt[b], 1u);
            if (p < CAP) { g_bu[b*CAP + p] = u; g_bidx[b*CAP + p] = j0 + k; }
        }
    }
}

// ---------------- kernel 3b: boundary fine-rank -----------------------------
__global__ void __launch_bounds__(256) fine_kernel(float* __restrict__ out) {
    if (!g_flag) return;
    const int b = blockIdx.x;
    if (g_T[b] < 0) return;

    __shared__ unsigned s_u[2048];
    __shared__ int      s_idx[2048];

    const unsigned mraw = g_bcnt[b];
    const unsigned S = g_S[b];
    const unsigned cutoff = g_cutoff;

    if (mraw <= 2048) {
        const int m = (int)mraw;
        for (int a = threadIdx.x; a < m; a += 256) {
            s_u[a] = g_bu[b*CAP + a];
            s_idx[a] = g_bidx[b*CAP + a];
        }
        __syncthreads();
        for (int a = threadIdx.x; a < m; a += 256) {
            unsigned ua = s_u[a]; int ia = s_idx[a];
            unsigned cnt = S;
            for (int k = 0; k < m; ++k) {
                unsigned ub = s_u[k];
                if (ub > ua || (ub == ua && s_idx[k] < ia)) cnt++;
            }
            if (cnt >= cutoff) out[((size_t)b*NN + ia)*5] = -1.0f;
        }
    } else {
        const int T = g_T[b];
        const unsigned* row = g_ubuf + (size_t)b*NN;
        for (int a = threadIdx.x; a < NN; a += 256) {
            unsigned ua = row[a];
            if (ua == SENT || (int)(ua >> 10) != T) continue;
            unsigned cnt = S;
            for (int jx = 0; jx < NN; ++jx) {
                unsigned uj = row[jx];
                if (uj != SENT && (int)(uj >> 10) == T &&
                    (uj > ua || (uj == ua && jx < a))) cnt++;
            }
            if (cnt >= cutoff) out[((size_t)b*NN + a)*5] = -1.0f;
        }
    }
}

// ---------------- launch ----------------------------------------------------
extern "C" void kernel_launch(void* const* d_in, const int* in_sizes, int n_in,
                              void* d_out, int out_size) {
    const float* gt      = (const float*)d_in[1];
    const float* anchors = (const float*)d_in[2];
    for (int k = 0; k < n_in; ++k) {
        if (in_sizes[k] == BB*GG*4) gt      = (const float*)d_in[k];
        if (in_sizes[k] == NN*4)    anchors = (const float*)d_in[k];
    }
    float* out = (float*)d_out;

    zero_kernel<<<128, 256>>>();
    dim3 mgrid(HH/4, AA, BB);              // 16 x 12 x 16 = 3072 blocks
    main_kernel<<<mgrid, 256>>>(gt, anchors, out);
    scan_kernel<<<BB, 256>>>();
    dim3 bgrid(NN/1024, BB);
    bulk_kernel<<<bgrid, 256>>>(out);
    fine_kernel<<<BB, 256>>>(out);
}

// round 7
// speedup vs baseline: 1.4997x; 1.1237x over previous
#include <cuda_runtime.h>
#include <stdint.h>

#define BB 16
#define AA 12
#define HH 64
#define WW 64
#define GG 64
#define NN (AA*HH*WW)        /* 49152 anchors per batch */
#define TOT (BB*NN)          /* 786432 */
#define NBUCK 1024
#define SENT 0xFFFFFFFFu
#define CAP  4096
#define ROWBLKS 48           /* bulk blocks per row: 48*256*4 = 49152 */

// ---------------- scratch (static __device__, no allocation) ----------------
__device__ unsigned g_ubuf[TOT];        // 23-bit mantissa of r for label-0, else SENT
__device__ unsigned g_hist[BB*NBUCK];   // per-row histogram over u>>13
__device__ unsigned g_pos, g_neg;
__device__ int      g_T[BB];            // boundary bucket (-1 = no disable in row)
__device__ unsigned g_S[BB];            // count strictly above boundary bucket
__device__ unsigned g_cutoff;
__device__ int      g_flag;             // neg_cnt > cutoff
__device__ unsigned g_bcnt[BB];
__device__ unsigned g_done[BB];
__device__ unsigned g_bu [BB*CAP];
__device__ int      g_bidx[BB*CAP];

// ------- Threefry-2x32-20, key=(0,42), PARTITIONABLE layout -----------------
__device__ __forceinline__ unsigned threefry_bits(unsigned i) {
    unsigned x0 = 0u, x1 = i;
    const unsigned k0 = 0u, k1 = 42u, k2 = 0x1BD11BDAu ^ 0u ^ 42u;
    x0 += k0; x1 += k1;
#define TFR(r) { x0 += x1; x1 = __funnelshift_l(x1, x1, (r)); x1 ^= x0; }
    TFR(13) TFR(15) TFR(26) TFR(6)   x0 += k1; x1 += k2 + 1u;
    TFR(17) TFR(29) TFR(16) TFR(24)  x0 += k2; x1 += k0 + 2u;
    TFR(13) TFR(15) TFR(26) TFR(6)   x0 += k0; x1 += k1 + 3u;
    TFR(17) TFR(29) TFR(16) TFR(24)  x0 += k1; x1 += k2 + 4u;
    TFR(13) TFR(15) TFR(26) TFR(6)   x0 += k2; x1 += k0 + 5u;
#undef TFR
    return x0 ^ x1;
}

// ---------------- kernel 0: zero scratch ------------------------------------
__global__ void zero_kernel() {
    int i = blockIdx.x * blockDim.x + threadIdx.x;   // 16*256 = 4096
    ((uint4*)g_hist)[i] = make_uint4(0u,0u,0u,0u);   // 4096 uint4 = 16384 words
    if (i < BB) { g_bcnt[i] = 0u; g_done[i] = 0u; }
    if (i == 0) { g_pos = 0u; g_neg = 0u; }
}

// ---------------- kernel 1: IoU / labels / targets / PRNG / hist ------------
// Block = 256 threads = (i_grp 0..3) x (j 0..63); each thread owns 4 rows
// i = i0 + i_grp*4 + rr. Fixed a = blockIdx.y, b = blockIdx.z, i0 = bx*16.
// Separable IoU (meshgrid anchors): iw[g][j], ih[g][row], u0[g]=aarea+ga with
// aarea block-constant. Division-free guard; exact __fdiv_rn on guard hit keeps
// bit-identity with the reference. Label-0 elements are written as -1
// tentatively; the restore pass flips the kept ones back to 0.
__global__ void __launch_bounds__(256) main_kernel(
        const float* __restrict__ gt,       // (B,G,4)
        const float* __restrict__ anchors,  // (N,4)
        float* __restrict__ out)            // (B,N,5)
{
    __shared__ float4 s_gb[GG];          // (gx0, gy0, gx1, gy1)
    __shared__ float  s_ga[GG];
    __shared__ float4 s_g0[GG];          // raw batch-0 gt boxes (targets quirk)
    __shared__ float  s_ax0[WW], s_ax1[WW];
    __shared__ float  s_ay0[16], s_ay1[16];
    __shared__ float  s_u0[GG];          // aarea + ga
    __shared__ float  s_iw[GG*WW];       // [g][j], 16KB
    __shared__ float4 s_ihp[GG*4];       // [g][i_grp] -> ih for 4 rows, 4KB
    __shared__ float  s_out[16*64*5];    // 20KB staged output

    const int b  = blockIdx.z;
    const int a  = blockIdx.y;
    const int i0 = blockIdx.x * 16;
    const int t  = threadIdx.x;
    const int j  = t & 63;
    const int ig = t >> 6;

    const float4* anc4 = (const float4*)anchors;

    // ---- phase 1: stage ----
    if (t < GG) {
        const float4 gp = *(const float4*)(gt + ((size_t)b*GG + t)*4);
        s_gb[t] = make_float4(gp.x, gp.y,
                              __fadd_rn(gp.x, gp.z), __fadd_rn(gp.y, gp.w));
        s_ga[t] = __fmul_rn(gp.z, gp.w);
    } else if (t < 2*GG) {
        s_g0[t - GG] = *(const float4*)(gt + (size_t)(t - GG)*4);  // batch 0
    } else if (t < 192) {
        int jj = t - 128;
        float4 v = anc4[(a*HH + i0)*WW + jj];   // x0(j), i-invariant
        s_ax0[jj] = v.x;
        s_ax1[jj] = __fadd_rn(v.x, v.z);
    } else if (t < 208) {
        int k = t - 192;
        float4 v = anc4[(a*HH + i0 + k)*WW];    // y0(i), j-invariant
        s_ay0[k] = v.y;
        s_ay1[k] = __fadd_rn(v.y, v.w);
    }
    const float4 A0 = anc4[(size_t)(a*HH + i0)*WW];  // w,h block-constant
    const float aw = A0.z, ah = A0.w;
    const float aarea = __fmul_rn(aw, ah);
    __syncthreads();

    // ---- phase 2: separable precompute ----
    if (t < GG) s_u0[t] = __fadd_rn(aarea, s_ga[t]);
    {   // ih packed: g = j, rows ig*4 .. ig*4+3
        const float4 gb = s_gb[j];
        float4 ihv;
        ihv.x = fmaxf(0.f, __fsub_rn(fminf(s_ay1[ig*4+0], gb.w), fmaxf(s_ay0[ig*4+0], gb.y)));
        ihv.y = fmaxf(0.f, __fsub_rn(fminf(s_ay1[ig*4+1], gb.w), fmaxf(s_ay0[ig*4+1], gb.y)));
        ihv.z = fmaxf(0.f, __fsub_rn(fminf(s_ay1[ig*4+2], gb.w), fmaxf(s_ay0[ig*4+2], gb.y)));
        ihv.w = fmaxf(0.f, __fsub_rn(fminf(s_ay1[ig*4+3], gb.w), fmaxf(s_ay0[ig*4+3], gb.y)));
        s_ihp[j*4 + ig] = ihv;
    }
    {   // iw: 16 g's per thread
        const float ax0 = s_ax0[j], ax1 = s_ax1[j];
#pragma unroll
        for (int r = 0; r < 16; ++r) {
            int g = ig*16 + r;
            const float4 gb = s_gb[g];
            s_iw[g*64 + j] = fmaxf(0.f, __fsub_rn(fminf(ax1, gb.z), fmaxf(ax0, gb.x)));
        }
    }
    __syncthreads();

    // ---- main loop: 4 rows per thread ----
    float best[4] = {-1.f,-1.f,-1.f,-1.f};
    float bsl [4] = {-1.f,-1.f,-1.f,-1.f};
    int   bg  [4] = {0,0,0,0};

#pragma unroll 4
    for (int g = 0; g < GG; ++g) {
        const float  iw  = s_iw[g*64 + j];
        const float4 ihv = s_ihp[g*4 + ig];
        const float  u0  = s_u0[g];
        const float ihs[4] = {ihv.x, ihv.y, ihv.z, ihv.w};
#pragma unroll
        for (int rr = 0; rr < 4; ++rr) {
            float inter = __fmul_rn(iw, ihs[rr]);
            float uni   = __fsub_rn(u0, inter);
            if (__fmaf_rn(-bsl[rr], uni, inter) >= 0.f) {   // conservative, rare
                float ov = __fdiv_rn(inter, uni);
                if (ov == 0.f) ov = 1e-10f;
                if (ov > best[rr]) {
                    best[rr] = ov; bg[rr] = g;
                    bsl[rr] = __fmul_rn(best[rr], 0.99999952f); // 1 - 2^-21
                }
            }
        }
    }

    // ---- epilogue ----
    const float L = 63.0f;
    const float x0 = s_ax0[j], ax1v = s_ax1[j];
    const bool keep_x =
        (x0 >= 0.f) && (aw >= 0.f) && (ah >= 0.f) &&
        (x0 <= L) && (__fsub_rn(ax1v, 1.0f) <= L);

    int myp = 0, myn = 0;
#pragma unroll
    for (int rr = 0; rr < 4; ++rr) {
        const int il = ig*4 + rr;            // row in block 0..15
        const float y0 = s_ay0[il], ay1v = s_ay1[il];
        const bool keep = keep_x && (y0 >= 0.f) && (y0 <= L) &&
                          (__fsub_rn(ay1v, 1.0f) <= L);

        float label = -1.0f;
        bool lab0 = false;
        if (keep) {
            if (best[rr] >= 0.7f)       label = 1.0f;
            else if (best[rr] <= 0.3f)  lab0 = true;   // tentative -1 (restore later)
            myp += (best[rr] > 0.7f);
            myn += (best[rr] < 0.3f);
        }

        float* so = s_out + (il*64 + j)*5;
        so[0] = label;                        // lab0 -> -1 tentatively
        if (keep) {
            const float4 g0 = s_g0[bg[rr]];
            so[1] = __fsub_rn(x0, __fmul_rn(g0.x, 0.0625f));
            so[2] = __fsub_rn(y0, __fmul_rn(g0.y, 0.0625f));
            so[3] = __fsub_rn(aw, __fmul_rn(g0.z, 0.0625f));
            so[4] = __fsub_rn(ah, __fmul_rn(g0.w, 0.0625f));
        } else {
            so[1] = 0.f; so[2] = 0.f; so[3] = 0.f; so[4] = 0.f;
        }

        const int n = (a*HH + (i0 + il))*WW + j;
        const size_t i_glob = (size_t)b*NN + n;
        unsigned u = SENT;
        if (lab0) {
            u = threefry_bits((unsigned)i_glob) >> 9;
            atomicAdd(&g_hist[b*NBUCK + (u >> 13)], 1u);
        }
        g_ubuf[i_glob] = u;                   // coalesced per row
    }

    for (int o = 16; o > 0; o >>= 1) {
        myp += __shfl_down_sync(0xFFFFFFFFu, myp, o);
        myn += __shfl_down_sync(0xFFFFFFFFu, myn, o);
    }
    if ((t & 31) == 0) {
        if (myp) atomicAdd(&g_pos, (unsigned)myp);
        if (myn) atomicAdd(&g_neg, (unsigned)myn);
    }

    __syncthreads();
    // coalesced write: block covers 16*64 = 1024 contiguous anchors = 1280 float4
    const float4* so4 = (const float4*)s_out;
    float4* o4 = (float4*)(out + (size_t)(((b*AA + a)*HH + i0)*WW)*5);
#pragma unroll
    for (int k = 0; k < 5; ++k) o4[k*256 + t] = so4[k*256 + t];
}

// ---------------- kernel 2: parallel boundary-bucket search -----------------
__global__ void __launch_bounds__(256) scan_kernel() {
    const int b = blockIdx.x;
    const int t = threadIdx.x;

    if (t == 0) g_T[b] = -1;                 // re-init every call (graph replay!)

    const unsigned pos = g_pos, negc = g_neg;
    const unsigned cutoff = (unsigned)max(1, 3 * (int)pos);
    if (b == 0 && t == 0) {
        g_cutoff = cutoff;
        g_flag   = (negc > cutoff) ? 1 : 0;
    }
    if (negc <= cutoff) return;

    const unsigned* hrow = g_hist + b*NBUCK;
    const int hi = (NBUCK - 1) - t*4;        // descending chunk of 4
    unsigned v0 = hrow[hi], v1 = hrow[hi-1], v2 = hrow[hi-2], v3 = hrow[hi-3];
    unsigned s = v0 + v1 + v2 + v3;

    __shared__ unsigned sh[256];
    sh[t] = s;
    __syncthreads();
    for (int o = 1; o < 256; o <<= 1) {
        unsigned add = (t >= o) ? sh[t - o] : 0u;
        __syncthreads();
        sh[t] += add;
        __syncthreads();
    }
    const unsigned incl = sh[t];
    const unsigned excl = incl - s;

    if (excl < cutoff && incl >= cutoff) {   // unique thread
        unsigned acc = excl;
        int T = hi; unsigned S = excl;
        const unsigned vs[4] = {v0, v1, v2, v3};
#pragma unroll
        for (int k = 0; k < 4; ++k) {
            if (acc + vs[k] >= cutoff) { T = hi - k; S = acc; break; }
            acc += vs[k];
        }
        g_T[b] = T; g_S[b] = S;
    }
}

// ---------------- kernel 3: restore kept negatives (bulk + fused fine) ------
// main wrote -1 for all label-0. Restore 0.0 for: all (if no disable), else
// bucket > T, else boundary-bucket elements with exact rank < cutoff.
__global__ void __launch_bounds__(256) restore_kernel(float* __restrict__ out) {
    const int b = blockIdx.y;
    const int flag = g_flag;
    const int T = g_T[b];
    const bool restore_all = (!flag) || (T < 0);

    const unsigned* row = g_ubuf + (size_t)b*NN;
    const int j0 = (blockIdx.x * 256 + threadIdx.x) * 4;
    const uint4 u4 = *(const uint4*)(row + j0);
    const unsigned uv[4] = {u4.x, u4.y, u4.z, u4.w};

#pragma unroll
    for (int k = 0; k < 4; ++k) {
        unsigned u = uv[k];
        if (u == SENT) continue;
        if (restore_all) {
            out[((size_t)b*NN + (j0 + k))*5] = 0.0f;
        } else {
            int bucket = (int)(u >> 13);
            if (bucket > T) {
                out[((size_t)b*NN + (j0 + k))*5] = 0.0f;   // rank < cutoff for sure
            } else if (bucket == T) {
                unsigned p = atomicAdd(&g_bcnt[b], 1u);
                if (p < CAP) { g_bu[b*CAP + p] = u; g_bidx[b*CAP + p] = j0 + k; }
            }
        }
    }

    if (restore_all) return;

    // ---- fused fine-rank: last block of this row does it ----
    __threadfence();
    __shared__ bool last;
    if (threadIdx.x == 0)
        last = (atomicAdd(&g_done[b], 1u) == ROWBLKS - 1u);
    __syncthreads();
    if (!last) return;

    __shared__ unsigned s_u[2048];
    __shared__ int      s_idx[2048];

    const unsigned mraw  = g_bcnt[b];
    const unsigned S     = g_S[b];
    const unsigned cutoff = g_cutoff;

    if (mraw <= 2048) {
        const int m = (int)mraw;
        for (int a = threadIdx.x; a < m; a += 256) {
            s_u[a]  = g_bu[b*CAP + a];
            s_idx[a] = g_bidx[b*CAP + a];
        }
        __syncthreads();
        for (int a = threadIdx.x; a < m; a += 256) {
            unsigned ua = s_u[a]; int ia = s_idx[a];
            unsigned cnt = S;
            for (int k = 0; k < m; ++k) {
                unsigned ub = s_u[k];
                if (ub > ua || (ub == ua && s_idx[k] < ia)) cnt++;
            }
            if (cnt < cutoff) out[((size_t)b*NN + ia)*5] = 0.0f;   // kept
        }
    } else {
        // Degenerate fallback: full-row exact rank on the boundary bucket.
        for (int a = threadIdx.x; a < NN; a += 256) {
            unsigned ua = row[a];
            if (ua == SENT || (int)(ua >> 13) != T) continue;
            unsigned cnt = S;
            for (int jx = 0; jx < NN; ++jx) {
                unsigned uj = row[jx];
                if (uj != SENT && (int)(uj >> 13) == T &&
                    (uj > ua || (uj == ua && jx < a))) cnt++;
            }
            if (cnt < cutoff) out[((size_t)b*NN + a)*5] = 0.0f;
        }
    }
}

// ---------------- launch ----------------------------------------------------
extern "C" void kernel_launch(void* const* d_in, const int* in_sizes, int n_in,
                              void* d_out, int out_size) {
    const float* gt      = (const float*)d_in[1];
    const float* anchors = (const float*)d_in[2];
    for (int k = 0; k < n_in; ++k) {
        if (in_sizes[k] == BB*GG*4) gt      = (const float*)d_in[k];
        if (in_sizes[k] == NN*4)    anchors = (const float*)d_in[k];
    }
    float* out = (float*)d_out;

    zero_kernel<<<16, 256>>>();
    dim3 mgrid(HH/16, AA, BB);             // 4 x 12 x 16 = 768 blocks
    main_kernel<<<mgrid, 256>>>(gt, anchors, out);
    scan_kernel<<<BB, 256>>>();
    dim3 rgrid(ROWBLKS, BB);               // 48 x 16
    restore_kernel<<<rgrid, 256>>>(out);
}

// round 8
// speedup vs baseline: 1.5210x; 1.0142x over previous
#include <cuda_runtime.h>
#include <stdint.h>

#define BB 16
#define AA 12
#define HH 64
#define WW 64
#define GG 64
#define NN (AA*HH*WW)        /* 49152 anchors per batch */
#define TOT (BB*NN)          /* 786432 */
#define NBUCK 1024
#define SENT 0xFFFFFFFFu
#define SLOTS 128
#define RBX 12               /* restore blocks per row */

// ---------------- scratch (static __device__, no allocation) ----------------
__device__ unsigned g_ubuf[TOT];                       // fallback store of u
__device__ unsigned g_hist[BB*NBUCK];                  // counts (u>>13)
__device__ unsigned long long g_list[(size_t)BB*NBUCK*SLOTS]; // (u<<32)|idx, 16MB
__device__ unsigned g_pos, g_neg;
__device__ int      g_T[BB];
__device__ unsigned g_S[BB];
__device__ unsigned g_cutoff;
__device__ int      g_flag;

// ------- Threefry-2x32-20, key=(0,42), PARTITIONABLE layout -----------------
__device__ __forceinline__ unsigned threefry_bits(unsigned i) {
    unsigned x0 = 0u, x1 = i;
    const unsigned k0 = 0u, k1 = 42u, k2 = 0x1BD11BDAu ^ 0u ^ 42u;
    x0 += k0; x1 += k1;
#define TFR(r) { x0 += x1; x1 = __funnelshift_l(x1, x1, (r)); x1 ^= x0; }
    TFR(13) TFR(15) TFR(26) TFR(6)   x0 += k1; x1 += k2 + 1u;
    TFR(17) TFR(29) TFR(16) TFR(24)  x0 += k2; x1 += k0 + 2u;
    TFR(13) TFR(15) TFR(26) TFR(6)   x0 += k0; x1 += k1 + 3u;
    TFR(17) TFR(29) TFR(16) TFR(24)  x0 += k1; x1 += k2 + 4u;
    TFR(13) TFR(15) TFR(26) TFR(6)   x0 += k2; x1 += k0 + 5u;
#undef TFR
    return x0 ^ x1;
}

// ---------------- kernel 0: zero scratch ------------------------------------
__global__ void zero_kernel() {
    int i = blockIdx.x * blockDim.x + threadIdx.x;   // 4096 threads
    ((uint4*)g_hist)[i] = make_uint4(0u,0u,0u,0u);   // 16384 words
    if (i == 0) { g_pos = 0u; g_neg = 0u; }
}

// ---------------- kernel 1: IoU / labels / targets / PRNG / lists -----------
// Block = (jt, a, b): 64 rows x 8 columns. Warp w owns column j = jt*8 + w;
// lane l owns rows l and l+32. iw is warp-uniform per g -> phase 2 compacts
// the g's with iw>0 into a per-column list (~25% of 64); zero-inter g's enter
// the argmax as the reference's 1e-10 value via first-zero-index merge.
// Division-free guard; exact __fdiv_rn on guard hit => bit-identical results.
// Label-0 written as -1 tentatively; restore pass flips kept ones back to 0.
__global__ void __launch_bounds__(256) main_kernel(
        const float* __restrict__ gt,       // (B,G,4)
        const float* __restrict__ anchors,  // (N,4)
        float* __restrict__ out)            // (B,N,5)
{
    __shared__ float4 s_gb[GG];          // (gx0, gy0, gx1, gy1)
    __shared__ float4 s_g0[GG];          // raw batch-0 gt boxes (targets quirk)
    __shared__ float  s_ga[GG];
    __shared__ float  s_u0[GG];          // aarea + ga
    __shared__ float  s_ax0[8], s_ax1[8];
    __shared__ float  s_ay0[HH], s_ay1[HH];
    __shared__ float  s_iw[8*GG];        // [jl][g]
    __shared__ float2 s_ih2[GG*32];      // [g][l] -> (ih row l, ih row l+32)
    __shared__ unsigned char s_lg[8*GG]; // compacted g indices per column
    __shared__ int    s_nl[8], s_fza[8]; // list length, first iw==0 g
    __shared__ float  s_out[HH*8*5];     // staged output (2560 floats)
    __shared__ unsigned s_ub[HH*8];      // staged u
    __shared__ unsigned s_p, s_n;

    const int b  = blockIdx.z;
    const int a  = blockIdx.y;
    const int jt = blockIdx.x;
    const int j0 = jt * 8;
    const int t  = threadIdx.x;
    const int w  = t >> 5;               // local column
    const int l  = t & 31;

    const float4* anc4 = (const float4*)anchors;

    // ---- phase 1: stage ----
    if (t == 0) { s_p = 0u; s_n = 0u; }
    if (t < GG) {
        const float4 gp = *(const float4*)(gt + ((size_t)b*GG + t)*4);
        s_gb[t] = make_float4(gp.x, gp.y,
                              __fadd_rn(gp.x, gp.z), __fadd_rn(gp.y, gp.w));
        s_ga[t] = __fmul_rn(gp.z, gp.w);
    } else if (t < 2*GG) {
        s_g0[t - GG] = *(const float4*)(gt + (size_t)(t - GG)*4);   // batch 0
    } else if (t < 136) {
        int k = t - 128;
        float4 v = anc4[a*HH*WW + j0 + k];      // x0(j): i-invariant
        s_ax0[k] = v.x; s_ax1[k] = __fadd_rn(v.x, v.z);
    } else if (t >= 192) {
        int i = t - 192;
        float4 v = anc4[(a*HH + i)*WW];         // y0(i): j-invariant
        s_ay0[i] = v.y; s_ay1[i] = __fadd_rn(v.y, v.w);
    }
    const float4 A0 = anc4[a*HH*WW];            // w,h constant per a
    const float aw = A0.z, ah = A0.w;
    const float aarea = __fmul_rn(aw, ah);
    __syncthreads();

    // ---- phase 2: separable precompute ----
    if (t < GG) s_u0[t] = __fadd_rn(aarea, s_ga[t]);
#pragma unroll
    for (int k = 0; k < 2; ++k) {               // iw: 512 entries
        int idx = t + k*256;
        int g = idx & 63, jl = idx >> 6;
        const float4 gb = s_gb[g];
        s_iw[jl*64 + g] = fmaxf(0.f, __fsub_rn(fminf(s_ax1[jl], gb.z),
                                               fmaxf(s_ax0[jl], gb.x)));
    }
#pragma unroll
    for (int k = 0; k < 8; ++k) {               // ih2: 2048 float2 entries
        int idx = t + k*256;
        int g = idx >> 5, ll = idx & 31;
        const float4 gb = s_gb[g];
        float v0 = fmaxf(0.f, __fsub_rn(fminf(s_ay1[ll],    gb.w), fmaxf(s_ay0[ll],    gb.y)));
        float v1 = fmaxf(0.f, __fsub_rn(fminf(s_ay1[ll+32], gb.w), fmaxf(s_ay0[ll+32], gb.y)));
        s_ih2[g*32 + ll] = make_float2(v0, v1);
    }
    __syncthreads();

    // ---- compaction: list of g with iw>0 for this warp's column ----
    {
        float iwA = s_iw[w*64 + l];
        float iwB = s_iw[w*64 + 32 + l];
        unsigned b0 = __ballot_sync(0xFFFFFFFFu, iwA > 0.f);
        unsigned b1 = __ballot_sync(0xFFFFFFFFu, iwB > 0.f);
        int cnt0 = __popc(b0);
        if (b0 & (1u << l)) s_lg[w*64 + __popc(b0 & ((1u<<l)-1u))] = (unsigned char)l;
        if (b1 & (1u << l)) s_lg[w*64 + cnt0 + __popc(b1 & ((1u<<l)-1u))] = (unsigned char)(l + 32);
        if (l == 0) {
            s_nl[w] = cnt0 + __popc(b1);
            unsigned nb0 = ~b0, nb1 = ~b1;
            int fz = 64;
            if (nb0)      fz = __ffs(nb0) - 1;
            else if (nb1) fz = 32 + __ffs(nb1) - 1;
            s_fza[w] = fz;
        }
    }
    __syncwarp();

    // ---- main loop over compacted list (ascending g) ----
    const int nl = s_nl[w];
    float best0 = -1.f, bsl0 = -1.f; int bg0 = 0, fz0 = 64;
    float best1 = -1.f, bsl1 = -1.f; int bg1 = 0, fz1 = 64;

    for (int s = 0; s < nl; ++s) {
        const int   g  = (int)s_lg[w*64 + s];
        const float iw = s_iw[w*64 + g];
        const float2 ih = s_ih2[g*32 + l];
        const float u0 = s_u0[g];
        {   // row l
            float inter = __fmul_rn(iw, ih.x);
            if (inter == 0.f) { if (fz0 == 64) fz0 = g; }
            else {
                float uni = __fsub_rn(u0, inter);
                if (__fmaf_rn(-bsl0, uni, inter) >= 0.f) {   // conservative, rare
                    float ov = __fdiv_rn(inter, uni);
                    if (ov == 0.f) ov = 1e-10f;
                    if (ov > best0) {
                        best0 = ov; bg0 = g;
                        bsl0 = __fmul_rn(best0, 0.99999952f); // 1 - 2^-21
                    }
                }
            }
        }
        {   // row l+32
            float inter = __fmul_rn(iw, ih.y);
            if (inter == 0.f) { if (fz1 == 64) fz1 = g; }
            else {
                float uni = __fsub_rn(u0, inter);
                if (__fmaf_rn(-bsl1, uni, inter) >= 0.f) {
                    float ov = __fdiv_rn(inter, uni);
                    if (ov == 0.f) ov = 1e-10f;
                    if (ov > best1) {
                        best1 = ov; bg1 = g;
                        bsl1 = __fmul_rn(best1, 0.99999952f);
                    }
                }
            }
        }
    }
    // merge zero-candidates (value 1e-10 at first zero-inter index)
    {
        int fz = min(s_fza[w], fz0);
        if (fz < 64) {
            if (best0 < 1e-10f)                     { best0 = 1e-10f; bg0 = fz; }
            else if (best0 == 1e-10f && fz < bg0)   bg0 = fz;
        }
        fz = min(s_fza[w], fz1);
        if (fz < 64) {
            if (best1 < 1e-10f)                     { best1 = 1e-10f; bg1 = fz; }
            else if (best1 == 1e-10f && fz < bg1)   bg1 = fz;
        }
    }

    // ---- epilogue ----
    const float L = 63.0f;
    const float x0 = s_ax0[w];
    const bool keep_x = (x0 >= 0.f) && (aw >= 0.f) && (ah >= 0.f) &&
                        (x0 <= L) && (__fsub_rn(s_ax1[w], 1.0f) <= L);
    int myp = 0, myn = 0;

#pragma unroll
    for (int rr = 0; rr < 2; ++rr) {
        const int   i    = rr ? (l + 32) : l;
        const float best = rr ? best1 : best0;
        const int   bg   = rr ? bg1 : bg0;
        const float y0 = s_ay0[i];
        const bool keep = keep_x && (y0 >= 0.f) && (y0 <= L) &&
                          (__fsub_rn(s_ay1[i], 1.0f) <= L);

        float label = -1.0f; bool lab0 = false;
        if (keep) {
            if (best >= 0.7f)       label = 1.0f;
            else if (best <= 0.3f)  lab0 = true;   // tentative -1
            myp += (best > 0.7f);
            myn += (best < 0.3f);
        }

        float* so = s_out + (i*8 + w)*5;
        so[0] = label;
        if (keep) {
            const float4 g0 = s_g0[bg];
            so[1] = __fsub_rn(x0, __fmul_rn(g0.x, 0.0625f));
            so[2] = __fsub_rn(y0, __fmul_rn(g0.y, 0.0625f));
            so[3] = __fsub_rn(aw, __fmul_rn(g0.z, 0.0625f));
            so[4] = __fsub_rn(ah, __fmul_rn(g0.w, 0.0625f));
        } else {
            so[1] = 0.f; so[2] = 0.f; so[3] = 0.f; so[4] = 0.f;
        }

        const int n = (a*HH + i)*WW + (j0 + w);
        unsigned u = SENT;
        if (lab0) {
            u = threefry_bits((unsigned)(b*NN + n)) >> 9;
            int bucket = (int)(u >> 13);
            unsigned slot = atomicAdd(&g_hist[b*NBUCK + bucket], 1u);
            if (slot < SLOTS)
                g_list[((size_t)(b*NBUCK + bucket))*SLOTS + slot] =
                    ((unsigned long long)u << 32) | (unsigned)n;
        }
        s_ub[i*8 + w] = u;
    }

    for (int o = 16; o > 0; o >>= 1) {
        myp += __shfl_down_sync(0xFFFFFFFFu, myp, o);
        myn += __shfl_down_sync(0xFFFFFFFFu, myn, o);
    }
    if (l == 0) {
        if (myp) atomicAdd(&s_p, (unsigned)myp);
        if (myn) atomicAdd(&s_n, (unsigned)myn);
    }
    __syncthreads();
    if (t == 0) {
        if (s_p) atomicAdd(&g_pos, s_p);
        if (s_n) atomicAdd(&g_neg, s_n);
    }

    // ---- staged writes ----
    const float4* so4 = (const float4*)s_out;
    float4* o4 = (float4*)out;
    const size_t obase = (size_t)(b*AA + a) * 5120;   // HH*WW*5/4
#pragma unroll
    for (int k = 0; k < 3; ++k) {
        int f = t + k*256;
        if (f < 640) {
            int i = f / 10, p = f % 10;
            o4[obase + (size_t)i*80 + jt*10 + p] = so4[f];
        }
    }
    if (t < 128) {
        int i = t >> 1, part = t & 1;
        const uint4* su4 = (const uint4*)s_ub;
        uint4* u4 = (uint4*)g_ubuf;
        u4[((size_t)b*NN + a*HH*WW)/4 + (size_t)i*16 + jt*2 + part] = su4[t];
    }
}

// ---------------- kernel 2: parallel boundary-bucket search -----------------
__global__ void __launch_bounds__(256) scan_kernel() {
    const int b = blockIdx.x;
    const int t = threadIdx.x;

    if (t == 0) g_T[b] = -1;

    const unsigned pos = g_pos, negc = g_neg;
    const unsigned cutoff = (unsigned)max(1, 3 * (int)pos);
    if (b == 0 && t == 0) {
        g_cutoff = cutoff;
        g_flag   = (negc > cutoff) ? 1 : 0;
    }
    if (negc <= cutoff) return;

    const unsigned* hrow = g_hist + b*NBUCK;
    const int hi = (NBUCK - 1) - t*4;
    unsigned v0 = hrow[hi], v1 = hrow[hi-1], v2 = hrow[hi-2], v3 = hrow[hi-3];
    unsigned s = v0 + v1 + v2 + v3;

    __shared__ unsigned sh[256];
    sh[t] = s;
    __syncthreads();
    for (int o = 1; o < 256; o <<= 1) {
        unsigned add = (t >= o) ? sh[t - o] : 0u;
        __syncthreads();
        sh[t] += add;
        __syncthreads();
    }
    const unsigned incl = sh[t];
    const unsigned excl = incl - s;

    if (excl < cutoff && incl >= cutoff) {   // unique thread
        unsigned acc = excl;
        int T = hi; unsigned S = excl;
        const unsigned vs[4] = {v0, v1, v2, v3};
#pragma unroll
        for (int k = 0; k < 4; ++k) {
            if (acc + vs[k] >= cutoff) { T = hi - k; S = acc; break; }
            acc += vs[k];
        }
        g_T[b] = T; g_S[b] = S;
    }
}

// ---------------- kernel 3: restore kept negatives --------------------------
// main wrote -1 for all label-0. If no disable: restore all (g_ubuf scan,
// RBX blocks/row). Else: restore buckets > T from the per-bucket lists and
// fine-rank bucket T (tiny). Overflow -> g_ubuf fallback for that row.
__global__ void __launch_bounds__(256) restore_kernel(float* __restrict__ out) {
    const int b = blockIdx.y;
    const int flag = g_flag;
    const int T = g_T[b];
    const unsigned* row = g_ubuf + (size_t)b*NN;

    if (!flag || T < 0) {
        // restore_all: this row's RBX blocks scan g_ubuf
        const int base4 = blockIdx.x * 1024;            // uint4 index
        const uint4* r4 = (const uint4*)row;
#pragma unroll
        for (int k = 0; k < 4; ++k) {
            int f = base4 + threadIdx.x + k*256;
            uint4 u4 = r4[f];
            int j = f*4;
            if (u4.x != SENT) out[((size_t)b*NN + j+0)*5] = 0.0f;
            if (u4.y != SENT) out[((size_t)b*NN + j+1)*5] = 0.0f;
            if (u4.z != SENT) out[((size_t)b*NN + j+2)*5] = 0.0f;
            if (u4.w != SENT) out[((size_t)b*NN + j+3)*5] = 0.0f;
        }
        return;
    }

    if (blockIdx.x != 0) return;
    const unsigned cutoff = g_cutoff;
    const unsigned S = g_S[b];

    __shared__ int s_ovf;
    if (threadIdx.x == 0) s_ovf = 0;
    __syncthreads();
    for (int q = T + threadIdx.x; q < NBUCK; q += 256)
        if (g_hist[b*NBUCK + q] > SLOTS) s_ovf = 1;
    __syncthreads();

    if (!s_ovf) {
        // buckets > T: all entries have rank < cutoff -> restore
        for (int q = T + 1 + threadIdx.x; q < NBUCK; q += 256) {
            unsigned c = g_hist[b*NBUCK + q];
            const unsigned long long* lst = g_list + ((size_t)(b*NBUCK + q))*SLOTS;
            for (unsigned e = 0; e < c; ++e) {
                unsigned idx = (unsigned)(lst[e] & 0xFFFFFFFFu);
                out[((size_t)b*NN + idx)*5] = 0.0f;
            }
        }
        // boundary bucket: exact rank
        __shared__ unsigned s_u[SLOTS];
        __shared__ unsigned s_i[SLOTS];
        const unsigned cT = g_hist[b*NBUCK + T];
        const unsigned long long* lst = g_list + ((size_t)(b*NBUCK + T))*SLOTS;
        for (unsigned e = threadIdx.x; e < cT; e += 256) {
            unsigned long long p = lst[e];
            s_u[e] = (unsigned)(p >> 32);
            s_i[e] = (unsigned)(p & 0xFFFFFFFFu);
        }
        __syncthreads();
        for (unsigned e = threadIdx.x; e < cT; e += 256) {
            unsigned ua = s_u[e], ia = s_i[e];
            unsigned cnt = S;
            for (unsigned k = 0; k < cT; ++k) {
                unsigned ub = s_u[k];
                if (ub > ua || (ub == ua && s_i[k] < ia)) cnt++;
            }
            if (cnt < cutoff) out[((size_t)b*NN + ia)*5] = 0.0f;   // kept
        }
    } else {
        // overflow fallback: full-row scan via g_ubuf
        for (int j = threadIdx.x; j < NN; j += 256) {
            unsigned u = row[j];
            if (u != SENT && (int)(u >> 13) > T)
                out[((size_t)b*NN + j)*5] = 0.0f;
        }
        for (int a = threadIdx.x; a < NN; a += 256) {
            unsigned ua = row[a];
            if (ua == SENT || (int)(ua >> 13) != T) continue;
            unsigned cnt = S;
            for (int jx = 0; jx < NN; ++jx) {
                unsigned uj = row[jx];
                if (uj != SENT && (int)(uj >> 13) == T &&
                    (uj > ua || (uj == ua && jx < a))) cnt++;
            }
            if (cnt < cutoff) out[((size_t)b*NN + a)*5] = 0.0f;
        }
    }
}

// ---------------- launch ----------------------------------------------------
extern "C" void kernel_launch(void* const* d_in, const int* in_sizes, int n_in,
                              void* d_out, int out_size) {
    const float* gt      = (const float*)d_in[1];
    const float* anchors = (const float*)d_in[2];
    for (int k = 0; k < n_in; ++k) {
        if (in_sizes[k] == BB*GG*4) gt      = (const float*)d_in[k];
        if (in_sizes[k] == NN*4)    anchors = (const float*)d_in[k];
    }
    float* out = (float*)d_out;

    zero_kernel<<<16, 256>>>();
    dim3 mgrid(8, AA, BB);                 // 8 j-tiles x 12 a x 16 b = 1536
    main_kernel<<<mgrid, 256>>>(gt, anchors, out);
    scan_kernel<<<BB, 256>>>();
    dim3 rgrid(RBX, BB);
    restore_kernel<<<rgrid, 256>>>(out);
}

// round 10
// speedup vs baseline: 1.6497x; 1.0846x over previous
#include <cuda_runtime.h>
#include <stdint.h>

#define BB 16
#define AA 12
#define HH 64
#define WW 64
#define GG 64
#define NN (AA*HH*WW)        /* 49152 anchors per batch */
#define TOT (BB*NN)          /* 786432 */
#define NBUCK 1024
#define SENT 0xFFFFFFFFu
#define SLOTS 128
#define RBX 12               /* restore blocks per row */

// ---------------- scratch (static __device__, no allocation) ----------------
__device__ unsigned g_ubuf[TOT];                       // fallback store of u
__device__ unsigned g_hist[BB*NBUCK];                  // counts (u>>13)
__device__ unsigned long long g_list[(size_t)BB*NBUCK*SLOTS]; // (u<<32)|idx
__device__ unsigned g_pos, g_neg;
__device__ int      g_T[BB];
__device__ unsigned g_S[BB];
__device__ unsigned g_cutoff;
__device__ int      g_flag;

// ------- Threefry-2x32-20, key=(0,42), PARTITIONABLE layout -----------------
__device__ __forceinline__ unsigned threefry_bits(unsigned i) {
    unsigned x0 = 0u, x1 = i;
    const unsigned k0 = 0u, k1 = 42u, k2 = 0x1BD11BDAu ^ 0u ^ 42u;
    x0 += k0; x1 += k1;
#define TFR(r) { x0 += x1; x1 = __funnelshift_l(x1, x1, (r)); x1 ^= x0; }
    TFR(13) TFR(15) TFR(26) TFR(6)   x0 += k1; x1 += k2 + 1u;
    TFR(17) TFR(29) TFR(16) TFR(24)  x0 += k2; x1 += k0 + 2u;
    TFR(13) TFR(15) TFR(26) TFR(6)   x0 += k0; x1 += k1 + 3u;
    TFR(17) TFR(29) TFR(16) TFR(24)  x0 += k1; x1 += k2 + 4u;
    TFR(13) TFR(15) TFR(26) TFR(6)   x0 += k2; x1 += k0 + 5u;
#undef TFR
    return x0 ^ x1;
}

// ---------------- kernel 0: zero scratch ------------------------------------
__global__ void zero_kernel() {
    int i = blockIdx.x * blockDim.x + threadIdx.x;   // 4096 threads
    ((uint4*)g_hist)[i] = make_uint4(0u,0u,0u,0u);   // 16384 words
    if (i == 0) { g_pos = 0u; g_neg = 0u; }
}

// ---------------- kernel 1: IoU / labels / targets / PRNG / lists -----------
// Block = (jt, a, b): 64 rows x 8 columns. Warp w owns column j = jt*8 + w;
// lane l owns rows l and l+32. iw is warp-uniform per g -> compacted g-list.
// Division-free guard; exact __fdiv_rn on guard hit => bit-identical results.
// Label-0 written as -1 tentatively; restore pass flips kept ones back to 0.
__global__ void __launch_bounds__(256) main_kernel(
        const float* __restrict__ gt,       // (B,G,4)
        const float* __restrict__ anchors,  // (N,4)
        float* __restrict__ out)            // (B,N,5)
{
    __shared__ float4 s_gb[GG];          // (gx0, gy0, gx1, gy1)
    __shared__ float4 s_g0[GG];          // raw batch-0 gt boxes (targets quirk)
    __shared__ float  s_ga[GG];
    __shared__ float  s_u0[GG];          // aarea + ga
    __shared__ float  s_ax0[8], s_ax1[8];
    __shared__ float  s_ay0[HH], s_ay1[HH];
    __shared__ float  s_iw[8*GG];        // [jl][g]
    __shared__ float2 s_ih2[GG*32];      // [g][l] -> (ih row l, ih row l+32)
    __shared__ unsigned char s_lg[8*GG]; // compacted g indices per column
    __shared__ int    s_nl[8], s_fza[8]; // list length, first iw==0 g
    __shared__ float  s_out[HH*8*5];     // staged output (2560 floats)
    __shared__ unsigned s_ub[HH*8];      // staged u
    __shared__ unsigned s_p, s_n;

    const int b  = blockIdx.z;
    const int a  = blockIdx.y;
    const int jt = blockIdx.x;
    const int j0 = jt * 8;
    const int t  = threadIdx.x;
    const int w  = t >> 5;               // local column
    const int l  = t & 31;

    const float4* anc4 = (const float4*)anchors;

    // ---- phase 1: stage ----
    if (t == 0) { s_p = 0u; s_n = 0u; }
    if (t < GG) {
        const float4 gp = *(const float4*)(gt + ((size_t)b*GG + t)*4);
        s_gb[t] = make_float4(gp.x, gp.y,
                              __fadd_rn(gp.x, gp.z), __fadd_rn(gp.y, gp.w));
        s_ga[t] = __fmul_rn(gp.z, gp.w);
    } else if (t < 2*GG) {
        s_g0[t - GG] = *(const float4*)(gt + (size_t)(t - GG)*4);   // batch 0
    } else if (t < 136) {
        int k = t - 128;
        float4 v = anc4[a*HH*WW + j0 + k];      // x0(j): i-invariant
        s_ax0[k] = v.x; s_ax1[k] = __fadd_rn(v.x, v.z);
    } else if (t >= 192) {
        int i = t - 192;
        float4 v = anc4[(a*HH + i)*WW];         // y0(i): j-invariant
        s_ay0[i] = v.y; s_ay1[i] = __fadd_rn(v.y, v.w);
    }
    const float4 A0 = anc4[a*HH*WW];            // w,h constant per a
    const float aw = A0.z, ah = A0.w;
    const float aarea = __fmul_rn(aw, ah);
    __syncthreads();

    // ---- phase 2: separable precompute ----
    if (t < GG) s_u0[t] = __fadd_rn(aarea, s_ga[t]);
#pragma unroll
    for (int k = 0; k < 2; ++k) {               // iw: 512 entries
        int idx = t + k*256;
        int g = idx & 63, jl = idx >> 6;
        const float4 gb = s_gb[g];
        s_iw[jl*64 + g] = fmaxf(0.f, __fsub_rn(fminf(s_ax1[jl], gb.z),
                                               fmaxf(s_ax0[jl], gb.x)));
    }
#pragma unroll
    for (int k = 0; k < 8; ++k) {               // ih2: 2048 float2 entries
        int idx = t + k*256;
        int g = idx >> 5, ll = idx & 31;
        const float4 gb = s_gb[g];
        float v0 = fmaxf(0.f, __fsub_rn(fminf(s_ay1[ll],    gb.w), fmaxf(s_ay0[ll],    gb.y)));
        float v1 = fmaxf(0.f, __fsub_rn(fminf(s_ay1[ll+32], gb.w), fmaxf(s_ay0[ll+32], gb.y)));
        s_ih2[g*32 + ll] = make_float2(v0, v1);
    }
    __syncthreads();

    // ---- compaction: list of g with iw>0 for this warp's column ----
    {
        float iwA = s_iw[w*64 + l];
        float iwB = s_iw[w*64 + 32 + l];
        unsigned b0 = __ballot_sync(0xFFFFFFFFu, iwA > 0.f);
        unsigned b1 = __ballot_sync(0xFFFFFFFFu, iwB > 0.f);
        int cnt0 = __popc(b0);
        if (b0 & (1u << l)) s_lg[w*64 + __popc(b0 & ((1u<<l)-1u))] = (unsigned char)l;
        if (b1 & (1u << l)) s_lg[w*64 + cnt0 + __popc(b1 & ((1u<<l)-1u))] = (unsigned char)(l + 32);
        if (l == 0) {
            s_nl[w] = cnt0 + __popc(b1);
            unsigned nb0 = ~b0, nb1 = ~b1;
            int fz = 64;
            if (nb0)      fz = __ffs(nb0) - 1;
            else if (nb1) fz = 32 + __ffs(nb1) - 1;
            s_fza[w] = fz;
        }
    }
    __syncwarp();

    // ---- main loop over compacted list (ascending g) ----
    const int nl = s_nl[w];
    float best0 = -1.f, bsl0 = -1.f; int bg0 = 0, fz0 = 64;
    float best1 = -1.f, bsl1 = -1.f; int bg1 = 0, fz1 = 64;

    for (int s = 0; s < nl; ++s) {
        const int   g  = (int)s_lg[w*64 + s];
        const float iw = s_iw[w*64 + g];
        const float2 ih = s_ih2[g*32 + l];
        const float u0 = s_u0[g];
        {   // row l
            float inter = __fmul_rn(iw, ih.x);
            if (inter == 0.f) { if (fz0 == 64) fz0 = g; }
            else {
                float uni = __fsub_rn(u0, inter);
                if (__fmaf_rn(-bsl0, uni, inter) >= 0.f) {   // conservative, rare
                    float ov = __fdiv_rn(inter, uni);
                    if (ov == 0.f) ov = 1e-10f;
                    if (ov > best0) {
                        best0 = ov; bg0 = g;
                        bsl0 = __fmul_rn(best0, 0.99999952f); // 1 - 2^-21
                    }
                }
            }
        }
        {   // row l+32
            float inter = __fmul_rn(iw, ih.y);
            if (inter == 0.f) { if (fz1 == 64) fz1 = g; }
            else {
                float uni = __fsub_rn(u0, inter);
                if (__fmaf_rn(-bsl1, uni, inter) >= 0.f) {
                    float ov = __fdiv_rn(inter, uni);
                    if (ov == 0.f) ov = 1e-10f;
                    if (ov > best1) {
                        best1 = ov; bg1 = g;
                        bsl1 = __fmul_rn(best1, 0.99999952f);
                    }
                }
            }
        }
    }
    // merge zero-candidates (value 1e-10 at first zero-inter index)
    {
        int fz = min(s_fza[w], fz0);
        if (fz < 64) {
            if (best0 < 1e-10f)                     { best0 = 1e-10f; bg0 = fz; }
            else if (best0 == 1e-10f && fz < bg0)   bg0 = fz;
        }
        fz = min(s_fza[w], fz1);
        if (fz < 64) {
            if (best1 < 1e-10f)                     { best1 = 1e-10f; bg1 = fz; }
            else if (best1 == 1e-10f && fz < bg1)   bg1 = fz;
        }
    }

    // ---- epilogue ----
    const float L = 63.0f;
    const float x0 = s_ax0[w];
    const bool keep_x = (x0 >= 0.f) && (aw >= 0.f) && (ah >= 0.f) &&
                        (x0 <= L) && (__fsub_rn(s_ax1[w], 1.0f) <= L);
    int myp = 0, myn = 0;

#pragma unroll
    for (int rr = 0; rr < 2; ++rr) {
        const int   i    = rr ? (l + 32) : l;
        const float best = rr ? best1 : best0;
        const int   bg   = rr ? bg1 : bg0;
        const float y0 = s_ay0[i];
        const bool keep = keep_x && (y0 >= 0.f) && (y0 <= L) &&
                          (__fsub_rn(s_ay1[i], 1.0f) <= L);

        float label = -1.0f; bool lab0 = false;
        if (keep) {
            if (best >= 0.7f)       label = 1.0f;
            else if (best <= 0.3f)  lab0 = true;   // tentative -1
            myp += (best > 0.7f);
            myn += (best < 0.3f);
        }

        float* so = s_out + (i*8 + w)*5;
        so[0] = label;
        if (keep) {
            const float4 g0 = s_g0[bg];
            so[1] = __fsub_rn(x0, __fmul_rn(g0.x, 0.0625f));
            so[2] = __fsub_rn(y0, __fmul_rn(g0.y, 0.0625f));
            so[3] = __fsub_rn(aw, __fmul_rn(g0.z, 0.0625f));
            so[4] = __fsub_rn(ah, __fmul_rn(g0.w, 0.0625f));
        } else {
            so[1] = 0.f; so[2] = 0.f; so[3] = 0.f; so[4] = 0.f;
        }

        const int n = (a*HH + i)*WW + (j0 + w);
        unsigned u = SENT;
        if (lab0) {
            u = threefry_bits((unsigned)(b*NN + n)) >> 9;
            int bucket = (int)(u >> 13);
            unsigned slot = atomicAdd(&g_hist[b*NBUCK + bucket], 1u);
            if (slot < SLOTS)
                g_list[((size_t)(b*NBUCK + bucket))*SLOTS + slot] =
                    ((unsigned long long)u << 32) | (unsigned)n;
        }
        s_ub[i*8 + w] = u;
    }

    for (int o = 16; o > 0; o >>= 1) {
        myp += __shfl_down_sync(0xFFFFFFFFu, myp, o);
        myn += __shfl_down_sync(0xFFFFFFFFu, myn, o);
    }
    if (l == 0) {
        if (myp) atomicAdd(&s_p, (unsigned)myp);
        if (myn) atomicAdd(&s_n, (unsigned)myn);
    }
    __syncthreads();
    if (t == 0) {
        if (s_p) atomicAdd(&g_pos, s_p);
        if (s_n) atomicAdd(&g_neg, s_n);
    }

    // ---- staged writes ----
    const float4* so4 = (const float4*)s_out;
    float4* o4 = (float4*)out;
    const size_t obase = (size_t)(b*AA + a) * 5120;   // HH*WW*5/4
#pragma unroll
    for (int k = 0; k < 3; ++k) {
        int f = t + k*256;
        if (f < 640) {
            int i = f / 10, p = f % 10;
            o4[obase + (size_t)i*80 + jt*10 + p] = so4[f];
        }
    }
    if (t < 128) {
        int i = t >> 1, part = t & 1;
        const uint4* su4 = (const uint4*)s_ub;
        uint4* u4 = (uint4*)g_ubuf;
        u4[((size_t)b*NN + a*HH*WW)/4 + (size_t)i*16 + jt*2 + part] = su4[t];
    }
}

// ---------------- kernel 2: parallel boundary-bucket search -----------------
__global__ void __launch_bounds__(256) scan_kernel() {
    const int b = blockIdx.x;
    const int t = threadIdx.x;

    if (t == 0) g_T[b] = -1;

    const unsigned pos = g_pos, negc = g_neg;
    const unsigned cutoff = (unsigned)max(1, 3 * (int)pos);
    if (b == 0 && t == 0) {
        g_cutoff = cutoff;
        g_flag   = (negc > cutoff) ? 1 : 0;
    }
    if (negc <= cutoff) return;

    const unsigned* hrow = g_hist + b*NBUCK;
    const int hi = (NBUCK - 1) - t*4;
    unsigned v0 = hrow[hi], v1 = hrow[hi-1], v2 = hrow[hi-2], v3 = hrow[hi-3];
    unsigned s = v0 + v1 + v2 + v3;

    __shared__ unsigned sh[256];
    sh[t] = s;
    __syncthreads();
    for (int o = 1; o < 256; o <<= 1) {
        unsigned add = (t >= o) ? sh[t - o] : 0u;
        __syncthreads();
        sh[t] += add;
        __syncthreads();
    }
    const unsigned incl = sh[t];
    const unsigned excl = incl - s;

    if (excl < cutoff && incl >= cutoff) {   // unique thread
        unsigned acc = excl;
        int T = hi; unsigned S = excl;
        const unsigned vs[4] = {v0, v1, v2, v3};
#pragma unroll
        for (int k = 0; k < 4; ++k) {
            if (acc + vs[k] >= cutoff) { T = hi - k; S = acc; break; }
            acc += vs[k];
        }
        g_T[b] = T; g_S[b] = S;
    }
}

// ---------------- kernel 3: restore kept negatives --------------------------
// main wrote -1 for all label-0. If no disable: restore all (g_ubuf scan).
// Else: buckets > T distributed over RBX blocks, entries over 256 threads;
// block bx==0 also fine-ranks bucket T. Overflow -> g_ubuf fallback (bx==0).
__global__ void __launch_bounds__(256) restore_kernel(float* __restrict__ out) {
    const int b  = blockIdx.y;
    const int bx = blockIdx.x;
    const int flag = g_flag;
    const int T = g_T[b];
    const unsigned* row = g_ubuf + (size_t)b*NN;

    if (!flag || T < 0) {
        // restore_all: this row's RBX blocks scan g_ubuf
        const int base4 = bx * 1024;                    // uint4 index
        const uint4* r4 = (const uint4*)row;
#pragma unroll
        for (int k = 0; k < 4; ++k) {
            int f = base4 + threadIdx.x + k*256;
            uint4 u4 = r4[f];
            int j = f*4;
            if (u4.x != SENT) out[((size_t)b*NN + j+0)*5] = 0.0f;
            if (u4.y != SENT) out[((size_t)b*NN + j+1)*5] = 0.0f;
            if (u4.z != SENT) out[((size_t)b*NN + j+2)*5] = 0.0f;
            if (u4.w != SENT) out[((size_t)b*NN + j+3)*5] = 0.0f;
        }
        return;
    }

    const unsigned cutoff = g_cutoff;
    const unsigned S = g_S[b];

    // overflow check (cheap, every block replicates it)
    __shared__ int s_ovf;
    if (threadIdx.x == 0) s_ovf = 0;
    __syncthreads();
    for (int q = T + threadIdx.x; q < NBUCK; q += 256)
        if (g_hist[b*NBUCK + q] > SLOTS) s_ovf = 1;
    __syncthreads();

    if (!s_ovf) {
        // buckets > T: distributed over blocks; entries over threads
        for (int q = T + 1 + bx; q < NBUCK; q += RBX) {
            const unsigned c = g_hist[b*NBUCK + q];
            const unsigned long long* lst = g_list + ((size_t)(b*NBUCK + q))*SLOTS;
            for (unsigned e = threadIdx.x; e < c; e += 256) {
                unsigned idx = (unsigned)(lst[e] & 0xFFFFFFFFu);
                out[((size_t)b*NN + idx)*5] = 0.0f;
            }
        }
        if (bx != 0) return;
        // boundary bucket: exact rank (c <= SLOTS)
        __shared__ unsigned s_u[SLOTS];
        __shared__ unsigned s_i[SLOTS];
        const unsigned cT = g_hist[b*NBUCK + T];
        const unsigned long long* lst = g_list + ((size_t)(b*NBUCK + T))*SLOTS;
        for (unsigned e = threadIdx.x; e < cT; e += 256) {
            unsigned long long p = lst[e];
            s_u[e] = (unsigned)(p >> 32);
            s_i[e] = (unsigned)(p & 0xFFFFFFFFu);
        }
        __syncthreads();
        for (unsigned e = threadIdx.x; e < cT; e += 256) {
            unsigned ua = s_u[e], ia = s_i[e];
            unsigned cnt = S;
            for (unsigned k = 0; k < cT; ++k) {
                unsigned ub = s_u[k];
                if (ub > ua || (ub == ua && s_i[k] < ia)) cnt++;
            }
            if (cnt < cutoff) out[((size_t)b*NN + ia)*5] = 0.0f;   // kept
        }
    } else {
        if (bx != 0) return;
        // overflow fallback: full-row scan via g_ubuf
        for (int j = threadIdx.x; j < NN; j += 256) {
            unsigned u = row[j];
            if (u != SENT && (int)(u >> 13) > T)
                out[((size_t)b*NN + j)*5] = 0.0f;
        }
        for (int a = threadIdx.x; a < NN; a += 256) {
            unsigned ua = row[a];
            if (ua == SENT || (int)(ua >> 13) != T) continue;
            unsigned cnt = S;
            for (int jx = 0; jx < NN; ++jx) {
                unsigned uj = row[jx];
                if (uj != SENT && (int)(uj >> 13) == T &&
                    (uj > ua || (uj == ua && jx < a))) cnt++;
            }
            if (cnt < cutoff) out[((size_t)b*NN + a)*5] = 0.0f;
        }
    }
}

// ---------------- launch ----------------------------------------------------
extern "C" void kernel_launch(void* const* d_in, const int* in_sizes, int n_in,
                              void* d_out, int out_size) {
    const float* gt      = (const float*)d_in[1];
    const float* anchors = (const float*)d_in[2];
    for (int k = 0; k < n_in; ++k) {
        if (in_sizes[k] == BB*GG*4) gt      = (const float*)d_in[k];
        if (in_sizes[k] == NN*4)    anchors = (const float*)d_in[k];
    }
    float* out = (float*)d_out;

    zero_kernel<<<16, 256>>>();
    dim3 mgrid(8, AA, BB);                 // 8 j-tiles x 12 a x 16 b = 1536
    main_kernel<<<mgrid, 256>>>(gt, anchors, out);
    scan_kernel<<<BB, 256>>>();
    dim3 rgrid(RBX, BB);
    restore_kernel<<<rgrid, 256>>>(out);
}